// round 7
// baseline (speedup 1.0000x reference)
#include <cuda_runtime.h>

// Problem constants (fixed by dataset)
#define NIMG 8
#define NCLS 21
#define NPIX 262144      // 512*512 = 2^18
#define NDIM 32
#define IGNORE_LAB 255
#define PSHIFT 18

#define GRID 1024                 // 128 blocks per image (one full wave)
#define NTHR 256
#define WARPS_PER_BLK 8
#define CHUNK 2048                // pixels per block (aligned inside one image)
#define PIX_PER_WARP (CHUNK / WARPS_PER_BLK)   // 256

// Scratch (__device__ globals; re-zeroed by the finalize block each call,
// initial state is zero from static init -> every call starts from zeros)
__device__ float        g_sums[NIMG * NCLS * NDIM];
__device__ float        g_counts[NIMG * NCLS];
__device__ double       g_scal[5];     // 0:ce 1:validcnt 2:var 3:inter 4:sumsq
__device__ unsigned int g_ctr;

__global__ __launch_bounds__(NTHR) void k_fused(const float* __restrict__ logit,
                                                const int* __restrict__ target,
                                                const float* __restrict__ feat,
                                                float* __restrict__ out) {
    __shared__ float acc[WARPS_PER_BLK][NCLS * NDIM];   // 21504 B
    __shared__ float csh[WARPS_PER_BLK][32];            // 1024 B (padded counts)
    __shared__ unsigned char slab[CHUNK];               // 2048 B label cache
    __shared__ float sred[5][WARPS_PER_BLK];
    __shared__ double dred[NTHR];                       // finalize reduce
    __shared__ bool is_last;

    const int tid  = threadIdx.x;
    const int lane = tid & 31;
    const int wid  = tid >> 5;
    const int n    = blockIdx.x >> 7;            // 128 blocks / image
    const int base = (blockIdx.x & 127) << 11;   // pixel offset within image

    // zero warp-private accumulators (no sync needed before phase B's sync)
    for (int idx = tid; idx < WARPS_PER_BLK * NCLS * NDIM; idx += NTHR)
        (&acc[0][0])[idx] = 0.f;
    (&csh[0][0])[tid] = 0.f;    // 256 = 8*32 exactly

    // ---------------- Phase A: logit pass over this block's 2048 pixels ----
    const int*   tg = target + ((size_t)n << PSHIFT) + base;
    const float* lp = logit + (size_t)n * NCLS * NPIX + base;

    float ce = 0.f, cnt = 0.f, var = 0.f, inter = 0.f;

    for (int i = tid; i < CHUNK; i += NTHR) {
        float v[NCLS];
#pragma unroll
        for (int c = 0; c < NCLS; c++) v[c] = __ldg(lp + (size_t)c * NPIX + i);

        float m = v[0];
#pragma unroll
        for (int c = 1; c < NCLS; c++) m = fmaxf(m, v[c]);

        float s = 0.f, tot = 0.f;
#pragma unroll
        for (int c = 0; c < NCLS; c++) {
            s += __expf(v[c] - m);
            tot += v[c];
        }
        float lse = m + __logf(s);

        int lab = __ldg(tg + i);
        slab[i] = (unsigned char)lab;        // cache for phase B

        if (lab != IGNORE_LAB) {
            float lg = v[0];
#pragma unroll
            for (int c = 1; c < NCLS; c++) lg = (c == lab) ? v[c] : lg;
            ce += (lse - lg);
            cnt += 1.f;
            var -= lg;
            inter += (tot - lg);
        }
    }
    __syncthreads();   // acc/csh zero + slab visible

    // ---------------- Phase B: feature pass, lane owns dim, warp owns pixels
    const float* fp = feat + (((size_t)n << PSHIFT) + base) * NDIM;
    const int p0 = wid * PIX_PER_WARP;

    float ssq = 0.f;
    float* myacc = &acc[wid][0];
    float* mycnt = &csh[wid][0];

#pragma unroll 1
    for (int p = p0; p < p0 + PIX_PER_WARP; p += 4) {
        int l0 = slab[p + 0], l1 = slab[p + 1], l2 = slab[p + 2], l3 = slab[p + 3];
        float f0 = fp[(size_t)(p + 0) * NDIM + lane];
        float f1 = fp[(size_t)(p + 1) * NDIM + lane];
        float f2 = fp[(size_t)(p + 2) * NDIM + lane];
        float f3 = fp[(size_t)(p + 3) * NDIM + lane];

        if (l0 != IGNORE_LAB) {
            myacc[l0 * NDIM + lane] += f0; ssq += f0 * f0;
            if (lane == 0) mycnt[l0] += 1.f;
        }
        if (l1 != IGNORE_LAB) {
            myacc[l1 * NDIM + lane] += f1; ssq += f1 * f1;
            if (lane == 0) mycnt[l1] += 1.f;
        }
        if (l2 != IGNORE_LAB) {
            myacc[l2 * NDIM + lane] += f2; ssq += f2 * f2;
            if (lane == 0) mycnt[l2] += 1.f;
        }
        if (l3 != IGNORE_LAB) {
            myacc[l3 * NDIM + lane] += f3; ssq += f3 * f3;
            if (lane == 0) mycnt[l3] += 1.f;
        }
    }

    // ---------------- block reduction of the 5 scalars -----------------
#pragma unroll
    for (int o = 16; o > 0; o >>= 1) {
        ce    += __shfl_down_sync(0xffffffffu, ce, o);
        cnt   += __shfl_down_sync(0xffffffffu, cnt, o);
        var   += __shfl_down_sync(0xffffffffu, var, o);
        inter += __shfl_down_sync(0xffffffffu, inter, o);
        ssq   += __shfl_down_sync(0xffffffffu, ssq, o);
    }
    if (lane == 0) {
        sred[0][wid] = ce; sred[1][wid] = cnt; sred[2][wid] = var;
        sred[3][wid] = inter; sred[4][wid] = ssq;
    }
    __syncthreads();   // warp bufs + sred complete

    if (tid == 0) {
        float a = 0, b = 0, c2 = 0, d2 = 0, e2 = 0;
#pragma unroll
        for (int w = 0; w < WARPS_PER_BLK; w++) {
            a += sred[0][w]; b += sred[1][w]; c2 += sred[2][w];
            d2 += sred[3][w]; e2 += sred[4][w];
        }
        atomicAdd(&g_scal[0], (double)a);
        atomicAdd(&g_scal[1], (double)b);
        atomicAdd(&g_scal[2], (double)c2);
        atomicAdd(&g_scal[3], (double)d2);
        atomicAdd(&g_scal[4], (double)e2);
    }

    // combine 8 warp buffers -> global partial sums
    for (int idx = tid; idx < NCLS * NDIM; idx += NTHR) {
        float s = 0.f;
#pragma unroll
        for (int w = 0; w < WARPS_PER_BLK; w++) s += acc[w][idx];
        atomicAdd(&g_sums[(size_t)n * NCLS * NDIM + idx], s);
    }
    if (tid < NCLS) {
        float s = 0.f;
#pragma unroll
        for (int w = 0; w < WARPS_PER_BLK; w++) s += csh[w][tid];
        atomicAdd(&g_counts[n * NCLS + tid], s);
    }

    // ---------------- last-block finalize + re-zero --------------------
    __threadfence();
    if (tid == 0) is_last = (atomicAdd(&g_ctr, 1u) == GRID - 1);
    __syncthreads();
    if (!is_last) return;
    __threadfence();   // acquire: other blocks' atomics visible via L2

    double center_neg = 0.0;
    for (int i = tid; i < NIMG * NCLS; i += NTHR) {
        double cntv = (double)__ldcg(&g_counts[i]);
        if (cntv > 0.0) {
            double m2 = 0.0;
            const float* s = &g_sums[(size_t)i * NDIM];
#pragma unroll
            for (int d = 0; d < NDIM; d++) {
                double sv = (double)__ldcg(s + d);
                m2 += sv * sv;
            }
            center_neg -= m2 / cntv;
        }
    }
    dred[tid] = center_neg;
    __syncthreads();
    for (int o = NTHR / 2; o > 0; o >>= 1) {
        if (tid < o) dred[tid] += dred[tid + o];
        __syncthreads();
    }
    if (tid == 0) {
        double s0 = __ldcg(&g_scal[0]), s1 = __ldcg(&g_scal[1]);
        double s2 = __ldcg(&g_scal[2]), s3 = __ldcg(&g_scal[3]);
        double s4 = __ldcg(&g_scal[4]);
        double denom = s1 > 1.0 ? s1 : 1.0;
        double CE = s0 / denom;
        double VAR = s2 / (double)NPIX;
        double Inter = s3 / (double)NPIX;
        double Center = (s4 + dred[0]) / (double)NPIX;
        double loss = (CE + 1.0 * VAR + 0.5 * Inter + 0.1 * Center) / (double)NIMG;
        out[0] = (float)loss;
    }
    __syncthreads();   // all reads of scratch done before re-zero

    // re-zero scratch so the next graph replay starts from a clean state
    for (int idx = tid; idx < NIMG * NCLS * NDIM; idx += NTHR) g_sums[idx] = 0.f;
    if (tid < NIMG * NCLS) g_counts[tid] = 0.f;
    if (tid < 5) g_scal[tid] = 0.0;
    if (tid == 0) g_ctr = 0u;
}

// ---------------------------------------------------------------------------
extern "C" void kernel_launch(void* const* d_in, const int* in_sizes, int n_in,
                              void* d_out, int out_size) {
    const float* logit = (const float*)d_in[0];
    const int* target = (const int*)d_in[1];
    const float* feat = (const float*)d_in[2];
    float* out = (float*)d_out;

    k_fused<<<GRID, NTHR>>>(logit, target, feat, out);
}

// round 8
// speedup vs baseline: 1.0823x; 1.0823x over previous
#include <cuda_runtime.h>

// Problem constants (fixed by dataset)
#define NIMG 8
#define NCLS 21
#define NPIX 262144      // 512*512 = 2^18
#define NDIM 32
#define IGNORE_LAB 255
#define PSHIFT 18

#define NTHR 256
#define WARPS_PER_BLK 8
#define ROLE_BLKS 1024            // per role: 128 blocks/image, 2048 px/block
#define GRID (2 * ROLE_BLKS)
#define CHUNK 2048
#define PIX_PER_WARP (CHUNK / WARPS_PER_BLK)   // 256

// Scratch (__device__ globals; re-zeroed by the finalize block each call;
// initial state is zero from static init -> every call starts from zeros)
__device__ float        g_sums[NIMG * NCLS * NDIM];
__device__ float        g_counts[NIMG * NCLS];
__device__ double       g_scal[5];     // 0:ce 1:validcnt 2:var 3:inter 4:sumsq
__device__ unsigned int g_ctr;

__global__ __launch_bounds__(NTHR) void k_fused(const float* __restrict__ logit,
                                                const int* __restrict__ target,
                                                const float* __restrict__ feat,
                                                float* __restrict__ out) {
    // Feature-role accumulators (logit-role blocks leave them untouched)
    __shared__ float  acc[WARPS_PER_BLK][NCLS * NDIM];  // 21504 B
    __shared__ float  csh[WARPS_PER_BLK][32];           // 1024 B
    __shared__ float  sred[5][WARPS_PER_BLK];           // 160 B
    __shared__ double dred[NTHR];                       // 2048 B (finalize only)
    __shared__ bool   is_last;

    const int tid  = threadIdx.x;
    const int lane = tid & 31;
    const int wid  = tid >> 5;

    const int role = blockIdx.x & 1;             // 0 = logit pass, 1 = feature pass
    const int idx  = blockIdx.x >> 1;            // 0..1023
    const int n    = idx >> 7;                   // image
    const int base = (idx & 127) << 11;          // pixel offset within image

    if (role == 0) {
        // ================= LOGIT ROLE (R4 k_logit body, chunked) ============
        const int*   tg = target + ((size_t)n << PSHIFT) + base;
        const float* lp = logit + (size_t)n * NCLS * NPIX + base;

        float ce = 0.f, cnt = 0.f, var = 0.f, inter = 0.f;

        for (int i = tid; i < CHUNK; i += NTHR) {
            float v[NCLS];
#pragma unroll
            for (int c = 0; c < NCLS; c++) v[c] = __ldg(lp + (size_t)c * NPIX + i);

            float m = v[0];
#pragma unroll
            for (int c = 1; c < NCLS; c++) m = fmaxf(m, v[c]);

            float s = 0.f, tot = 0.f;
#pragma unroll
            for (int c = 0; c < NCLS; c++) {
                s += __expf(v[c] - m);
                tot += v[c];
            }
            float lse = m + __logf(s);

            int lab = __ldg(tg + i);
            if (lab != IGNORE_LAB) {
                float lg = v[0];
#pragma unroll
                for (int c = 1; c < NCLS; c++) lg = (c == lab) ? v[c] : lg;
                ce += (lse - lg);
                cnt += 1.f;
                var -= lg;
                inter += (tot - lg);
            }
        }

#pragma unroll
        for (int o = 16; o > 0; o >>= 1) {
            ce    += __shfl_down_sync(0xffffffffu, ce, o);
            cnt   += __shfl_down_sync(0xffffffffu, cnt, o);
            var   += __shfl_down_sync(0xffffffffu, var, o);
            inter += __shfl_down_sync(0xffffffffu, inter, o);
        }
        if (lane == 0) {
            sred[0][wid] = ce; sred[1][wid] = cnt;
            sred[2][wid] = var; sred[3][wid] = inter;
        }
        __syncthreads();
        if (tid == 0) {
            float a = 0, b = 0, c2 = 0, d2 = 0;
#pragma unroll
            for (int w = 0; w < WARPS_PER_BLK; w++) {
                a += sred[0][w]; b += sred[1][w]; c2 += sred[2][w]; d2 += sred[3][w];
            }
            atomicAdd(&g_scal[0], (double)a);
            atomicAdd(&g_scal[1], (double)b);
            atomicAdd(&g_scal[2], (double)c2);
            atomicAdd(&g_scal[3], (double)d2);
        }
    } else {
        // ================= FEATURE ROLE (R4 k_feat body) ====================
        for (int i = tid; i < WARPS_PER_BLK * NCLS * NDIM; i += NTHR)
            (&acc[0][0])[i] = 0.f;
        (&csh[0][0])[tid] = 0.f;    // 256 = 8*32 exactly
        __syncthreads();

        const int*   tg = target + ((size_t)n << PSHIFT) + base;
        const float* fp = feat + (((size_t)n << PSHIFT) + base) * NDIM;
        const int p0 = wid * PIX_PER_WARP;

        float ssq = 0.f;
        float* myacc = &acc[wid][0];
        float* mycnt = &csh[wid][0];

#pragma unroll 1
        for (int p = p0; p < p0 + PIX_PER_WARP; p += 4) {
            int l0 = __ldg(tg + p + 0), l1 = __ldg(tg + p + 1);
            int l2 = __ldg(tg + p + 2), l3 = __ldg(tg + p + 3);
            float f0 = fp[(size_t)(p + 0) * NDIM + lane];
            float f1 = fp[(size_t)(p + 1) * NDIM + lane];
            float f2 = fp[(size_t)(p + 2) * NDIM + lane];
            float f3 = fp[(size_t)(p + 3) * NDIM + lane];

            if (l0 != IGNORE_LAB) {
                myacc[l0 * NDIM + lane] += f0; ssq += f0 * f0;
                if (lane == 0) mycnt[l0] += 1.f;
            }
            if (l1 != IGNORE_LAB) {
                myacc[l1 * NDIM + lane] += f1; ssq += f1 * f1;
                if (lane == 0) mycnt[l1] += 1.f;
            }
            if (l2 != IGNORE_LAB) {
                myacc[l2 * NDIM + lane] += f2; ssq += f2 * f2;
                if (lane == 0) mycnt[l2] += 1.f;
            }
            if (l3 != IGNORE_LAB) {
                myacc[l3 * NDIM + lane] += f3; ssq += f3 * f3;
                if (lane == 0) mycnt[l3] += 1.f;
            }
        }
        __syncthreads();

        // combine warp buffers -> global partials
        for (int i = tid; i < NCLS * NDIM; i += NTHR) {
            float s = 0.f;
#pragma unroll
            for (int w = 0; w < WARPS_PER_BLK; w++) s += acc[w][i];
            atomicAdd(&g_sums[(size_t)n * NCLS * NDIM + i], s);
        }
        if (tid < NCLS) {
            float s = 0.f;
#pragma unroll
            for (int w = 0; w < WARPS_PER_BLK; w++) s += csh[w][tid];
            atomicAdd(&g_counts[n * NCLS + tid], s);
        }

#pragma unroll
        for (int o = 16; o > 0; o >>= 1) ssq += __shfl_down_sync(0xffffffffu, ssq, o);
        if (lane == 0) sred[4][wid] = ssq;
        __syncthreads();
        if (tid == 0) {
            float s = 0.f;
#pragma unroll
            for (int w = 0; w < WARPS_PER_BLK; w++) s += sred[4][w];
            atomicAdd(&g_scal[4], (double)s);
        }
    }

    // ================= last-block finalize + re-zero ========================
    __threadfence();
    if (tid == 0) is_last = (atomicAdd(&g_ctr, 1u) == GRID - 1);
    __syncthreads();
    if (!is_last) return;
    __threadfence();   // acquire: other blocks' atomics visible via L2

    double center_neg = 0.0;
    for (int i = tid; i < NIMG * NCLS; i += NTHR) {
        double cntv = (double)__ldcg(&g_counts[i]);
        if (cntv > 0.0) {
            double m2 = 0.0;
            const float* s = &g_sums[(size_t)i * NDIM];
#pragma unroll
            for (int d = 0; d < NDIM; d++) {
                double sv = (double)__ldcg(s + d);
                m2 += sv * sv;
            }
            center_neg -= m2 / cntv;
        }
    }
    dred[tid] = center_neg;
    __syncthreads();
    for (int o = NTHR / 2; o > 0; o >>= 1) {
        if (tid < o) dred[tid] += dred[tid + o];
        __syncthreads();
    }
    if (tid == 0) {
        double s0 = __ldcg(&g_scal[0]), s1 = __ldcg(&g_scal[1]);
        double s2 = __ldcg(&g_scal[2]), s3 = __ldcg(&g_scal[3]);
        double s4 = __ldcg(&g_scal[4]);
        double denom = s1 > 1.0 ? s1 : 1.0;
        double CE = s0 / denom;
        double VAR = s2 / (double)NPIX;
        double Inter = s3 / (double)NPIX;
        double Center = (s4 + dred[0]) / (double)NPIX;
        double loss = (CE + 1.0 * VAR + 0.5 * Inter + 0.1 * Center) / (double)NIMG;
        out[0] = (float)loss;
    }
    __syncthreads();   // all reads of scratch done before re-zero

    for (int i = tid; i < NIMG * NCLS * NDIM; i += NTHR) g_sums[i] = 0.f;
    if (tid < NIMG * NCLS) g_counts[tid] = 0.f;
    if (tid < 5) g_scal[tid] = 0.0;
    if (tid == 0) g_ctr = 0u;
}

// ---------------------------------------------------------------------------
extern "C" void kernel_launch(void* const* d_in, const int* in_sizes, int n_in,
                              void* d_out, int out_size) {
    const float* logit = (const float*)d_in[0];
    const int* target = (const int*)d_in[1];
    const float* feat = (const float*)d_in[2];
    float* out = (float*)d_out;

    k_fused<<<GRID, NTHR>>>(logit, target, feat, out);
}

// round 9
// speedup vs baseline: 1.2829x; 1.1853x over previous
#include <cuda_runtime.h>

// Problem constants (fixed by dataset)
#define NIMG 8
#define NCLS 21
#define NPIX 262144      // 512*512 = 2^18
#define NDIM 32
#define IGNORE_LAB 255
#define PSHIFT 18

// Scratch (__device__ globals; finalize re-zeroes them each call; initial
// state is zero from static init -> every call starts from zeros)
__device__ float        g_sums[NIMG * NCLS * NDIM];
__device__ float        g_counts[NIMG * NCLS];
__device__ double       g_scal[5];     // 0:ce 1:validcnt 2:var 3:inter 4:sumsq
__device__ unsigned int g_ctr;

// ---------------------------------------------------------------------------
// Kernel 1: logit pass (R4 body, unchanged).  One pixel per thread,
// grid-stride.  1184 blocks = one full wave at 6 blocks/SM-ish.
// ---------------------------------------------------------------------------
__global__ __launch_bounds__(256) void k_logit(const float* __restrict__ logit,
                                               const int* __restrict__ target) {
    int tid = blockIdx.x * blockDim.x + threadIdx.x;
    int stride = gridDim.x * blockDim.x;

    float ce = 0.f, cnt = 0.f, var = 0.f, inter = 0.f;

    for (int g = tid; g < NIMG * NPIX; g += stride) {
        int n = g >> PSHIFT;
        int p = g & (NPIX - 1);
        const float* lp = logit + (size_t)n * NCLS * NPIX + p;

        float v[NCLS];
#pragma unroll
        for (int c = 0; c < NCLS; c++) v[c] = __ldcs(lp + (size_t)c * NPIX);

        float m = v[0];
#pragma unroll
        for (int c = 1; c < NCLS; c++) m = fmaxf(m, v[c]);

        float s = 0.f, tot = 0.f;
#pragma unroll
        for (int c = 0; c < NCLS; c++) {
            s += __expf(v[c] - m);
            tot += v[c];
        }
        float lse = m + __logf(s);

        int lab = __ldg(target + g);
        if (lab != IGNORE_LAB) {
            float lg = v[0];
#pragma unroll
            for (int c = 1; c < NCLS; c++) lg = (c == lab) ? v[c] : lg;
            ce += (lse - lg);
            cnt += 1.f;
            var -= lg;
            inter += (tot - lg);
        }
    }

    int lane = threadIdx.x & 31;
    int wid = threadIdx.x >> 5;
#pragma unroll
    for (int o = 16; o > 0; o >>= 1) {
        ce += __shfl_down_sync(0xffffffffu, ce, o);
        cnt += __shfl_down_sync(0xffffffffu, cnt, o);
        var += __shfl_down_sync(0xffffffffu, var, o);
        inter += __shfl_down_sync(0xffffffffu, inter, o);
    }
    __shared__ float sred[4][8];
    if (lane == 0) {
        sred[0][wid] = ce; sred[1][wid] = cnt; sred[2][wid] = var; sred[3][wid] = inter;
    }
    __syncthreads();
    if (threadIdx.x == 0) {
        float a = 0, b = 0, c2 = 0, d2 = 0;
#pragma unroll
        for (int w = 0; w < 8; w++) {
            a += sred[0][w]; b += sred[1][w]; c2 += sred[2][w]; d2 += sred[3][w];
        }
        atomicAdd(&g_scal[0], (double)a);
        atomicAdd(&g_scal[1], (double)b);
        atomicAdd(&g_scal[2], (double)c2);
        atomicAdd(&g_scal[3], (double)d2);
    }
}

// ---------------------------------------------------------------------------
// Kernel 2: feature pass (R4 body) + last-block finalize + scratch re-zero.
// grid = (128, 8), 256 threads (8 warps).  Counter counts 1024 blocks.
// ---------------------------------------------------------------------------
#define BLOCKS_PER_IMG 128
#define FEAT_GRID (BLOCKS_PER_IMG * NIMG)      // 1024
#define WARPS_PER_BLK 8
#define PIX_PER_WARP (NPIX / (BLOCKS_PER_IMG * WARPS_PER_BLK))   // 256

__global__ __launch_bounds__(256) void k_feat(const float* __restrict__ feat,
                                              const int* __restrict__ target,
                                              float* __restrict__ out) {
    __shared__ float acc[WARPS_PER_BLK][NCLS * NDIM];  // 21504 B
    __shared__ float csh[WARPS_PER_BLK][32];           // 1 KB
    __shared__ double dred[256];                       // finalize reduce
    __shared__ bool is_last;

    int lane = threadIdx.x & 31;
    int wid = threadIdx.x >> 5;
    int n = blockIdx.y;

    for (int idx = threadIdx.x; idx < WARPS_PER_BLK * NCLS * NDIM; idx += blockDim.x)
        (&acc[0][0])[idx] = 0.f;
    (&csh[0][0])[threadIdx.x] = 0.f;   // 256 = 8*32 exactly
    __syncthreads();

    int p0 = (blockIdx.x * WARPS_PER_BLK + wid) * PIX_PER_WARP;
    const int* tg = target + (size_t)n * NPIX;
    const float* fp = feat + (size_t)n * NPIX * NDIM;

    float ssq = 0.f;
    float* myacc = &acc[wid][0];
    float* mycnt = &csh[wid][0];

#pragma unroll 1
    for (int p = p0; p < p0 + PIX_PER_WARP; p += 4) {
        int l0 = __ldg(tg + p + 0), l1 = __ldg(tg + p + 1);
        int l2 = __ldg(tg + p + 2), l3 = __ldg(tg + p + 3);
        float f0 = __ldcs(fp + (size_t)(p + 0) * NDIM + lane);
        float f1 = __ldcs(fp + (size_t)(p + 1) * NDIM + lane);
        float f2 = __ldcs(fp + (size_t)(p + 2) * NDIM + lane);
        float f3 = __ldcs(fp + (size_t)(p + 3) * NDIM + lane);

        if (l0 != IGNORE_LAB) {
            myacc[l0 * NDIM + lane] += f0; ssq += f0 * f0;
            if (lane == 0) mycnt[l0] += 1.f;
        }
        if (l1 != IGNORE_LAB) {
            myacc[l1 * NDIM + lane] += f1; ssq += f1 * f1;
            if (lane == 0) mycnt[l1] += 1.f;
        }
        if (l2 != IGNORE_LAB) {
            myacc[l2 * NDIM + lane] += f2; ssq += f2 * f2;
            if (lane == 0) mycnt[l2] += 1.f;
        }
        if (l3 != IGNORE_LAB) {
            myacc[l3 * NDIM + lane] += f3; ssq += f3 * f3;
            if (lane == 0) mycnt[l3] += 1.f;
        }
    }
    __syncthreads();

    // combine 8 warp buffers -> global partials
    for (int idx = threadIdx.x; idx < NCLS * NDIM; idx += blockDim.x) {
        float s = 0.f;
#pragma unroll
        for (int w = 0; w < WARPS_PER_BLK; w++) s += acc[w][idx];
        atomicAdd(&g_sums[(size_t)n * NCLS * NDIM + idx], s);
    }
    if (threadIdx.x < NCLS) {
        float s = 0.f;
#pragma unroll
        for (int w = 0; w < WARPS_PER_BLK; w++) s += csh[w][threadIdx.x];
        atomicAdd(&g_counts[n * NCLS + threadIdx.x], s);
    }

#pragma unroll
    for (int o = 16; o > 0; o >>= 1) ssq += __shfl_down_sync(0xffffffffu, ssq, o);
    __shared__ float sq[8];
    if (lane == 0) sq[wid] = ssq;
    __syncthreads();
    if (threadIdx.x == 0) {
        float s = 0.f;
#pragma unroll
        for (int w = 0; w < WARPS_PER_BLK; w++) s += sq[w];
        atomicAdd(&g_scal[4], (double)s);
    }

    // ---------------- last-block finalize + re-zero ----------------------
    __threadfence();
    if (threadIdx.x == 0)
        is_last = (atomicAdd(&g_ctr, 1u) == FEAT_GRID - 1);
    __syncthreads();
    if (!is_last) return;
    __threadfence();   // acquire: all other blocks' atomics visible

    int tid = threadIdx.x;
    double center_neg = 0.0;
    for (int i = tid; i < NIMG * NCLS; i += 256) {
        double cntv = (double)__ldcg(&g_counts[i]);
        if (cntv > 0.0) {
            double m2 = 0.0;
            const float* s = &g_sums[(size_t)i * NDIM];
#pragma unroll
            for (int d = 0; d < NDIM; d++) {
                double sv = (double)__ldcg(s + d);
                m2 += sv * sv;
            }
            center_neg -= m2 / cntv;
        }
    }
    dred[tid] = center_neg;
    __syncthreads();
    for (int o = 128; o > 0; o >>= 1) {
        if (tid < o) dred[tid] += dred[tid + o];
        __syncthreads();
    }
    if (tid == 0) {
        double s0 = __ldcg(&g_scal[0]), s1 = __ldcg(&g_scal[1]);
        double s2 = __ldcg(&g_scal[2]), s3 = __ldcg(&g_scal[3]);
        double s4 = __ldcg(&g_scal[4]);
        double denom = s1 > 1.0 ? s1 : 1.0;
        double CE = s0 / denom;
        double VAR = s2 / (double)NPIX;
        double Inter = s3 / (double)NPIX;
        double Center = (s4 + dred[0]) / (double)NPIX;
        double loss = (CE + 1.0 * VAR + 0.5 * Inter + 0.1 * Center) / (double)NIMG;
        out[0] = (float)loss;
    }
    __syncthreads();   // all scratch reads complete before re-zero

    for (int i = tid; i < NIMG * NCLS * NDIM; i += 256) g_sums[i] = 0.f;
    if (tid < NIMG * NCLS) g_counts[tid] = 0.f;
    if (tid < 5) g_scal[tid] = 0.0;
    if (tid == 0) g_ctr = 0u;
}

// ---------------------------------------------------------------------------
extern "C" void kernel_launch(void* const* d_in, const int* in_sizes, int n_in,
                              void* d_out, int out_size) {
    const float* logit = (const float*)d_in[0];
    const int* target = (const int*)d_in[1];
    const float* feat = (const float*)d_in[2];
    float* out = (float*)d_out;

    k_logit<<<1184, 256>>>(logit, target);
    k_feat<<<dim3(BLOCKS_PER_IMG, NIMG), 256>>>(feat, target, out);
}